// round 14
// baseline (speedup 1.0000x reference)
#include <cuda_runtime.h>
#include <cuda_fp16.h>
#include <math.h>
#include <stdint.h>

#define B_   2
#define S_   2048
#define DM   1024
#define NH   16
#define DH   64
#define WIN  256
#define MT   (B_*S_)

// ---------------- scratch (__device__ globals; no allocs allowed) ----------
__device__ __half g_xh[(size_t)MT * DM];
__device__ __half g_wqT[(size_t)3*DM*DM];
__device__ __half g_woT[(size_t)DM*DM];
__device__ __half g_qkvh[(size_t)MT*3*DM];
__device__ __half g_ah[(size_t)MT*DM];

// ---------------- helpers ---------------------------------------------------
__device__ __forceinline__ uint32_t s2u(const void* p){
    uint32_t a;
    asm("{ .reg .u64 t; cvta.to.shared.u64 t, %1; cvt.u32.u64 %0, t; }":"=r"(a):"l"(p));
    return a;
}
__device__ __forceinline__ void cp16(uint32_t dst, const void* src){
    asm volatile("cp.async.cg.shared.global [%0], [%1], 16;"::"r"(dst),"l"(src));
}
__device__ __forceinline__ void ldsm_x4(uint32_t& r0,uint32_t& r1,uint32_t& r2,uint32_t& r3,uint32_t addr){
    asm volatile("ldmatrix.sync.aligned.m8n8.x4.shared.b16 {%0,%1,%2,%3}, [%4];"
        : "=r"(r0),"=r"(r1),"=r"(r2),"=r"(r3) : "r"(addr));
}
__device__ __forceinline__ void ldsm_x4t(uint32_t& r0,uint32_t& r1,uint32_t& r2,uint32_t& r3,uint32_t addr){
    asm volatile("ldmatrix.sync.aligned.m8n8.x4.trans.shared.b16 {%0,%1,%2,%3}, [%4];"
        : "=r"(r0),"=r"(r1),"=r"(r2),"=r"(r3) : "r"(addr));
}
__device__ __forceinline__ void mma16816(float* c, uint32_t a0,uint32_t a1,uint32_t a2,uint32_t a3,
                                         uint32_t b0,uint32_t b1){
    asm volatile("mma.sync.aligned.m16n8k16.row.col.f32.f16.f16.f32 "
        "{%0,%1,%2,%3}, {%4,%5,%6,%7}, {%8,%9}, {%0,%1,%2,%3};"
        : "+f"(c[0]),"+f"(c[1]),"+f"(c[2]),"+f"(c[3])
        : "r"(a0),"r"(a1),"r"(a2),"r"(a3),"r"(b0),"r"(b1));
}
__device__ __forceinline__ uint32_t packh2(float x, float y){
    __half2 h = __floats2half2_rn(x, y);
    return *(uint32_t*)&h;
}

// ---------------- merged prep kernel ----------------------------------------
// sections: [0,4096) fhalf x ; [4096,7168) thalf Wqkv ; [7168,8192) thalf Wout
__global__ __launch_bounds__(256) void prep_all(
    const float* __restrict__ x, const float* __restrict__ Wqkv,
    const float* __restrict__ Wout,
    __half* __restrict__ xh, __half* __restrict__ wq, __half* __restrict__ wo)
{
    __shared__ float t[32][33];
    const int bb = blockIdx.x;
    const int tid = threadIdx.x;

    if (bb < 4096){
        int i = (bb*256 + tid)*4;
        if (i >= MT*DM) return;
        float4 v = *(const float4*)(x + i);
        *(__half2*)(xh + i)     = __floats2half2_rn(v.x, v.y);
        *(__half2*)(xh + i + 2) = __floats2half2_rn(v.z, v.w);
        return;
    }

    const float* W; __half* Th; int K, N, idx;
    if (bb < 7168){ idx = bb - 4096; W = Wqkv; Th = wq; K = DM; N = 3*DM; }
    else          { idx = bb - 7168; W = Wout; Th = wo; K = DM; N = DM;   }
    const int xdim = N/32;
    const int n0 = (idx % xdim)*32, k0 = (idx / xdim)*32;
    const int tx = tid & 31, ty = tid >> 5;
#pragma unroll
    for (int i = 0; i < 32; i += 8)
        t[ty+i][tx] = W[(size_t)(k0+ty+i)*N + n0+tx];
    __syncthreads();
#pragma unroll
    for (int i = 0; i < 32; i += 8)
        Th[(size_t)(n0+ty+i)*K + k0+tx] = __float2half_rn(t[tx][ty+i]);
}

// ---------------- pure fp16 HMMA GEMM, fp32 accum, 3 CTAs/SM ----------------
#define BM 64
#define BN 128
#define BK 32
#define ROWB 80
#define OFF_A 0
#define OFF_B (BM*ROWB)
#define GSTAGE_BYTES ((BM+BN)*ROWB)          // 15360
#define GEMM_SMEM (3*GSTAGE_BYTES)           // 46080

__global__ __launch_bounds__(256, 3) void gemm_fp16(
    const __half* __restrict__ Ah, const __half* __restrict__ Bh,
    __half* __restrict__ Ch, float* __restrict__ Cf, int M, int N, int K)
{
    extern __shared__ char smraw[];
    const uint32_t sb = s2u(smraw);
    const int tid = threadIdx.x, lane = tid & 31, wid = tid >> 5;
    const int row0 = blockIdx.y * BM, col0 = blockIdx.x * BN;
    const int wm = (wid & 1) * 32;
    const int wn = (wid >> 1) * 32;
    const int nch = K / BK;

    const __half* pA = Ah + (size_t)row0 * K;
    const __half* pB = Bh + (size_t)col0 * K;

    const int lr = tid >> 2;
    const int lq = tid & 3;

    float acc[2][4][4];
#pragma unroll
    for (int f = 0; f < 2; f++)
#pragma unroll
        for (int j = 0; j < 4; j++)
#pragma unroll
            for (int i = 0; i < 4; i++) acc[f][j][i] = 0.f;

#define LOAD_STAGE(s_, c_)                                              \
    {                                                                   \
        uint32_t base_ = sb + (s_) * GSTAGE_BYTES;                      \
        size_t kof_ = (size_t)(c_) * BK;                                \
        uint32_t d_ = base_ + lr * ROWB + lq * 16;                      \
        size_t g_ = (size_t)lr * K + kof_ + lq * 8;                     \
        size_t g2_ = (size_t)(lr + 64) * K + kof_ + lq * 8;             \
        cp16(d_ + OFF_A, pA + g_);                                      \
        cp16(d_ + OFF_B, pB + g_);                                      \
        cp16(d_ + OFF_B + 64*ROWB, pB + g2_);                           \
    }

    LOAD_STAGE(0, 0);
    asm volatile("cp.async.commit_group;");
    LOAD_STAGE(1, 1);
    asm volatile("cp.async.commit_group;");

    for (int c = 0; c < nch; c++){
        asm volatile("cp.async.wait_group 1;");
        __syncthreads();

        if (c + 2 < nch){
            const int s2 = (c + 2) % 3;
            LOAD_STAGE(s2, c + 2);
        }
        asm volatile("cp.async.commit_group;");

        const uint32_t base = sb + (c % 3) * GSTAGE_BYTES;
#pragma unroll
        for (int ks = 0; ks < 2; ks++){
            const uint32_t kcol = (ks * 16 + (lane >> 4) * 8) * 2;
            uint32_t a[2][4], b[2][4];
#pragma unroll
            for (int f = 0; f < 2; f++){
                uint32_t ad = (wm + f * 16 + (lane & 15)) * ROWB + kcol;
                ldsm_x4(a[f][0], a[f][1], a[f][2], a[f][3], base + OFF_A + ad);
            }
#pragma unroll
            for (int g = 0; g < 2; g++){
                uint32_t bd = (wn + g * 16 + (lane & 15)) * ROWB + kcol;
                ldsm_x4(b[g][0], b[g][1], b[g][2], b[g][3], base + OFF_B + bd);
            }
#pragma unroll
            for (int f = 0; f < 2; f++)
#pragma unroll
                for (int j = 0; j < 4; j++){
                    const int g = j >> 1, o = j & 1;
                    mma16816(acc[f][j], a[f][0], a[f][1], a[f][2], a[f][3],
                             b[g][o], b[g][o + 2]);
                }
        }
    }

#pragma unroll
    for (int f = 0; f < 2; f++){
        const int row = row0 + wm + f * 16 + (lane >> 2);
#pragma unroll
        for (int j = 0; j < 4; j++){
            const int col = col0 + wn + j * 8 + (lane & 3) * 2;
            if (Cf){
                *(float2*)(Cf + (size_t)row * N + col)       = make_float2(acc[f][j][0], acc[f][j][1]);
                *(float2*)(Cf + (size_t)(row + 8) * N + col) = make_float2(acc[f][j][2], acc[f][j][3]);
            } else {
                *(uint32_t*)(Ch + (size_t)row * N + col)       = packh2(acc[f][j][0], acc[f][j][1]);
                *(uint32_t*)(Ch + (size_t)(row + 8) * N + col) = packh2(acc[f][j][2], acc[f][j][3]);
            }
        }
    }
}

// ---------------- fp16 flash attention: 128-q tile, 8 warps, warp skip ------
#define RWB 144
#define AQ 0
#define KVBASE (128*RWB)                 // 18432
#define KVSTAGE (2*64*RWB)               // 18432 (K + V)
#define ATTN_SMEM (KVBASE + 2*KVSTAGE)   // 55296

__global__ __launch_bounds__(256) void attn_hmma(
    const __half* __restrict__ qkv, __half* __restrict__ oh)
{
    extern __shared__ char smc[];
    const uint32_t sb = s2u(smc);
    const int tid = threadIdx.x, lane = tid & 31, wid = tid >> 5;
    const int qt = blockIdx.x, bhid = blockIdx.y;
    const int b = bhid >> 4, h = bhid & 15;
    const int qs = qt * 128;
    const int wm = wid * 16;
    const size_t tok0 = (size_t)b * S_;

    // ---- load Q tile (pre-scaled by 0.125, exact in fp16) ----
    {
        const __half* qb = qkv + (tok0 + qs) * 3072 + h * 64;
        const __half2 sc = __half2half2(__float2half_rn(0.125f));
        for (int i = tid; i < 1024; i += 256){
            int r = i >> 3, q = i & 7;
            uint4 v = *(const uint4*)(qb + (size_t)r*3072 + q*8);
            __half2* p = (__half2*)&v;
            p[0] = __hmul2(p[0], sc); p[1] = __hmul2(p[1], sc);
            p[2] = __hmul2(p[2], sc); p[3] = __hmul2(p[3], sc);
            *(uint4*)(smc + AQ + r*RWB + q*16) = v;
        }
    }
    __syncthreads();

    uint32_t aq[4][4];
#pragma unroll
    for (int ks = 0; ks < 4; ks++){
        uint32_t ad = (uint32_t)((wm + (lane & 15)) * RWB + (ks*16 + (lane >> 4)*8) * 2);
        ldsm_x4(aq[ks][0], aq[ks][1], aq[ks][2], aq[ks][3], sb + AQ + ad);
    }

    float oacc[8][4];
#pragma unroll
    for (int f = 0; f < 8; f++)
#pragma unroll
        for (int e = 0; e < 4; e++) oacc[f][e] = 0.f;
    float m0 = -1e30f, m1 = -1e30f, l0 = 0.f, l1 = 0.f;

    const int ilo = qs + wm + (lane >> 2);
    const int ihi = ilo + 8;
    const int rmin = qs + wm;
    const int rmax = qs + wm + 15;

    const int js = qs - (WIN - 1);
    const int t0 = js > 0 ? (js >> 6) : 0;
    const int qe = (qs + 127) >> 6;

#define KV_LOAD(s_, jb_)                                                 \
    {                                                                    \
        uint32_t kbase_ = sb + KVBASE + (uint32_t)((s_) * KVSTAGE);      \
        uint32_t vbase_ = kbase_ + 64*RWB;                               \
        _Pragma("unroll")                                                \
        for (int u_ = 0; u_ < 2; u_++){                                  \
            int i_ = tid + u_*256;                                       \
            int r_ = i_ >> 3, q_ = i_ & 7;                               \
            size_t g_ = (tok0 + (jb_) + r_) * 3072 + h*64 + q_*8;        \
            cp16(kbase_ + r_*RWB + q_*16, qkv + g_ + 1024);              \
            cp16(vbase_ + r_*RWB + q_*16, qkv + g_ + 2048);              \
        }                                                                \
    }

    KV_LOAD(0, t0 * 64);
    asm volatile("cp.async.commit_group;");

    for (int kt = t0; kt <= qe; kt++){
        const int jb = kt * 64;
        const int s = (kt - t0) & 1;
        asm volatile("cp.async.wait_group 0;");
        __syncthreads();

        if (kt + 1 <= qe){
            KV_LOAD(s ^ 1, jb + 64);
        }
        asm volatile("cp.async.commit_group;");

        // per-warp skip: tile fully outside [rmin-255, rmax] -> fully masked
        if (jb > rmax || jb + 63 < rmin - (WIN - 1)) continue;

        const uint32_t kb = sb + KVBASE + (uint32_t)(s * KVSTAGE);
        const uint32_t vb = kb + 64*RWB;

        float sacc[8][4];
#pragma unroll
        for (int f = 0; f < 8; f++)
#pragma unroll
            for (int e = 0; e < 4; e++) sacc[f][e] = 0.f;

#pragma unroll
        for (int g = 0; g < 4; g++){
#pragma unroll
            for (int ks = 0; ks < 4; ks++){
                uint32_t bd = (uint32_t)((g*16 + (lane & 15)) * RWB + (ks*16 + (lane >> 4)*8) * 2);
                uint32_t k0,k1,k2,k3;
                ldsm_x4(k0,k1,k2,k3, kb + bd);
                mma16816(sacc[2*g],   aq[ks][0],aq[ks][1],aq[ks][2],aq[ks][3], k0, k2);
                mma16816(sacc[2*g+1], aq[ks][0],aq[ks][1],aq[ks][2],aq[ks][3], k1, k3);
            }
        }

        float mx0 = -1e30f, mx1 = -1e30f;
#pragma unroll
        for (int f = 0; f < 8; f++){
            int c0 = jb + f*8 + 2*(lane & 3);
            int c1 = c0 + 1;
            sacc[f][0] = (c0 <= ilo && c0 > ilo - WIN) ? sacc[f][0] : -1e30f;
            sacc[f][1] = (c1 <= ilo && c1 > ilo - WIN) ? sacc[f][1] : -1e30f;
            sacc[f][2] = (c0 <= ihi && c0 > ihi - WIN) ? sacc[f][2] : -1e30f;
            sacc[f][3] = (c1 <= ihi && c1 > ihi - WIN) ? sacc[f][3] : -1e30f;
            mx0 = fmaxf(mx0, fmaxf(sacc[f][0], sacc[f][1]));
            mx1 = fmaxf(mx1, fmaxf(sacc[f][2], sacc[f][3]));
        }
        mx0 = fmaxf(mx0, __shfl_xor_sync(0xffffffffu, mx0, 1));
        mx0 = fmaxf(mx0, __shfl_xor_sync(0xffffffffu, mx0, 2));
        mx1 = fmaxf(mx1, __shfl_xor_sync(0xffffffffu, mx1, 1));
        mx1 = fmaxf(mx1, __shfl_xor_sync(0xffffffffu, mx1, 2));
        float mn0 = fmaxf(m0, mx0), mn1 = fmaxf(m1, mx1);
        float rc0 = __expf(m0 - mn0), rc1 = __expf(m1 - mn1);
        float rs0 = 0.f, rs1 = 0.f;
#pragma unroll
        for (int f = 0; f < 8; f++){
            sacc[f][0] = __expf(sacc[f][0] - mn0);
            sacc[f][1] = __expf(sacc[f][1] - mn0);
            sacc[f][2] = __expf(sacc[f][2] - mn1);
            sacc[f][3] = __expf(sacc[f][3] - mn1);
            rs0 += sacc[f][0] + sacc[f][1];
            rs1 += sacc[f][2] + sacc[f][3];
        }
        rs0 += __shfl_xor_sync(0xffffffffu, rs0, 1);
        rs0 += __shfl_xor_sync(0xffffffffu, rs0, 2);
        rs1 += __shfl_xor_sync(0xffffffffu, rs1, 1);
        rs1 += __shfl_xor_sync(0xffffffffu, rs1, 2);
        l0 = l0 * rc0 + rs0;  l1 = l1 * rc1 + rs1;
        m0 = mn0;  m1 = mn1;
#pragma unroll
        for (int f = 0; f < 8; f++){
            oacc[f][0] *= rc0; oacc[f][1] *= rc0;
            oacc[f][2] *= rc1; oacc[f][3] *= rc1;
        }

#pragma unroll
        for (int kk = 0; kk < 4; kk++){
            uint32_t pa[4];
            pa[0] = packh2(sacc[2*kk][0],   sacc[2*kk][1]);
            pa[1] = packh2(sacc[2*kk][2],   sacc[2*kk][3]);
            pa[2] = packh2(sacc[2*kk+1][0], sacc[2*kk+1][1]);
            pa[3] = packh2(sacc[2*kk+1][2], sacc[2*kk+1][3]);
#pragma unroll
            for (int j2 = 0; j2 < 4; j2++){
                uint32_t vd = (uint32_t)((kk*16 + ((lane >> 3) & 1)*8 + (lane & 7)) * RWB
                                         + (j2*16 + (lane >> 4)*8) * 2);
                uint32_t v0,v1,v2,v3;
                ldsm_x4t(v0,v1,v2,v3, vb + vd);
                mma16816(oacc[2*j2],   pa[0],pa[1],pa[2],pa[3], v0, v1);
                mma16816(oacc[2*j2+1], pa[0],pa[1],pa[2],pa[3], v2, v3);
            }
        }
    }

    float il0 = 1.f / l0, il1 = 1.f / l1;
    const int col = h*64 + 2*(lane & 3);
    size_t rowlo = (tok0 + ilo) * DM;
    size_t rowhi = (tok0 + ihi) * DM;
#pragma unroll
    for (int f = 0; f < 8; f++){
        *(uint32_t*)(oh + rowlo + col + f*8) = packh2(oacc[f][0]*il0, oacc[f][1]*il0);
        *(uint32_t*)(oh + rowhi + col + f*8) = packh2(oacc[f][2]*il1, oacc[f][3]*il1);
    }
}

// ---------------------------------------------------------------------------
extern "C" void kernel_launch(void* const* d_in, const int* in_sizes, int n_in,
                              void* d_out, int out_size)
{
    const float* x    = (const float*)d_in[0];
    const float* Wqkv = (const float*)d_in[1];
    const float* Wout = (const float*)d_in[2];
    float* out = (float*)d_out;

    __half *xh, *wq, *wo, *qkvh, *ah;
    cudaGetSymbolAddress((void**)&xh, g_xh);
    cudaGetSymbolAddress((void**)&wq, g_wqT);
    cudaGetSymbolAddress((void**)&wo, g_woT);
    cudaGetSymbolAddress((void**)&qkvh, g_qkvh);
    cudaGetSymbolAddress((void**)&ah, g_ah);

    cudaFuncSetAttribute(gemm_fp16, cudaFuncAttributeMaxDynamicSharedMemorySize, GEMM_SMEM);
    cudaFuncSetAttribute(attn_hmma, cudaFuncAttributeMaxDynamicSharedMemorySize, ATTN_SMEM);

    prep_all<<<8192, 256>>>(x, Wqkv, Wout, xh, wq, wo);
    gemm_fp16<<<dim3(3*DM/BN, MT/BM), 256, GEMM_SMEM>>>(xh, wq, qkvh, nullptr, MT, 3*DM, DM);
    attn_hmma<<<dim3(S_/128, B_*NH), 256, ATTN_SMEM>>>(qkvh, ah);
    gemm_fp16<<<dim3(DM/BN, MT/BM), 256, GEMM_SMEM>>>(ah, wo, nullptr, out, MT, DM, DM);
}

// round 15
// speedup vs baseline: 1.0458x; 1.0458x over previous
#include <cuda_runtime.h>
#include <cuda_fp16.h>
#include <math.h>
#include <stdint.h>

#define B_   2
#define S_   2048
#define DM   1024
#define NH   16
#define DH   64
#define WIN  256
#define MT   (B_*S_)

// ---------------- scratch (__device__ globals; no allocs allowed) ----------
__device__ __half g_xh[(size_t)MT * DM];
__device__ __half g_wqT[(size_t)3*DM*DM];
__device__ __half g_woT[(size_t)DM*DM];
__device__ __half g_qkvh[(size_t)MT*3*DM];
__device__ __half g_ah[(size_t)MT*DM];

// ---------------- helpers ---------------------------------------------------
__device__ __forceinline__ uint32_t s2u(const void* p){
    uint32_t a;
    asm("{ .reg .u64 t; cvta.to.shared.u64 t, %1; cvt.u32.u64 %0, t; }":"=r"(a):"l"(p));
    return a;
}
__device__ __forceinline__ void cp16(uint32_t dst, const void* src){
    asm volatile("cp.async.cg.shared.global [%0], [%1], 16;"::"r"(dst),"l"(src));
}
__device__ __forceinline__ void ldsm_x4(uint32_t& r0,uint32_t& r1,uint32_t& r2,uint32_t& r3,uint32_t addr){
    asm volatile("ldmatrix.sync.aligned.m8n8.x4.shared.b16 {%0,%1,%2,%3}, [%4];"
        : "=r"(r0),"=r"(r1),"=r"(r2),"=r"(r3) : "r"(addr));
}
__device__ __forceinline__ void ldsm_x4t(uint32_t& r0,uint32_t& r1,uint32_t& r2,uint32_t& r3,uint32_t addr){
    asm volatile("ldmatrix.sync.aligned.m8n8.x4.trans.shared.b16 {%0,%1,%2,%3}, [%4];"
        : "=r"(r0),"=r"(r1),"=r"(r2),"=r"(r3) : "r"(addr));
}
__device__ __forceinline__ void mma16816(float* c, uint32_t a0,uint32_t a1,uint32_t a2,uint32_t a3,
                                         uint32_t b0,uint32_t b1){
    asm volatile("mma.sync.aligned.m16n8k16.row.col.f32.f16.f16.f32 "
        "{%0,%1,%2,%3}, {%4,%5,%6,%7}, {%8,%9}, {%0,%1,%2,%3};"
        : "+f"(c[0]),"+f"(c[1]),"+f"(c[2]),"+f"(c[3])
        : "r"(a0),"r"(a1),"r"(a2),"r"(a3),"r"(b0),"r"(b1));
}
__device__ __forceinline__ uint32_t packh2(float x, float y){
    __half2 h = __floats2half2_rn(x, y);
    return *(uint32_t*)&h;
}

// ---------------- merged prep kernel ----------------------------------------
// sections: [0,4096) fhalf x ; [4096,7168) thalf Wqkv ; [7168,8192) thalf Wout
__global__ __launch_bounds__(256) void prep_all(
    const float* __restrict__ x, const float* __restrict__ Wqkv,
    const float* __restrict__ Wout,
    __half* __restrict__ xh, __half* __restrict__ wq, __half* __restrict__ wo)
{
    __shared__ float t[32][33];
    const int bb = blockIdx.x;
    const int tid = threadIdx.x;

    if (bb < 4096){
        int i = (bb*256 + tid)*4;
        if (i >= MT*DM) return;
        float4 v = *(const float4*)(x + i);
        *(__half2*)(xh + i)     = __floats2half2_rn(v.x, v.y);
        *(__half2*)(xh + i + 2) = __floats2half2_rn(v.z, v.w);
        return;
    }

    const float* W; __half* Th; int K, N, idx;
    if (bb < 7168){ idx = bb - 4096; W = Wqkv; Th = wq; K = DM; N = 3*DM; }
    else          { idx = bb - 7168; W = Wout; Th = wo; K = DM; N = DM;   }
    const int xdim = N/32;
    const int n0 = (idx % xdim)*32, k0 = (idx / xdim)*32;
    const int tx = tid & 31, ty = tid >> 5;
#pragma unroll
    for (int i = 0; i < 32; i += 8)
        t[ty+i][tx] = W[(size_t)(k0+ty+i)*N + n0+tx];
    __syncthreads();
#pragma unroll
    for (int i = 0; i < 32; i += 8)
        Th[(size_t)(n0+ty+i)*K + k0+tx] = __float2half_rn(t[tx][ty+i]);
}

// ---------------- pure fp16 HMMA GEMM, fp32 accum, 2 CTAs/SM (R13) ----------
#define BM 64
#define BN 128
#define BK 32
#define ROWB 80
#define OFF_A 0
#define OFF_B (BM*ROWB)
#define GSTAGE_BYTES ((BM+BN)*ROWB)          // 15360
#define GEMM_SMEM (3*GSTAGE_BYTES)           // 46080

__global__ __launch_bounds__(256, 2) void gemm_fp16(
    const __half* __restrict__ Ah, const __half* __restrict__ Bh,
    __half* __restrict__ Ch, float* __restrict__ Cf, int M, int N, int K)
{
    extern __shared__ char smraw[];
    const uint32_t sb = s2u(smraw);
    const int tid = threadIdx.x, lane = tid & 31, wid = tid >> 5;
    const int row0 = blockIdx.y * BM, col0 = blockIdx.x * BN;
    const int wm = (wid & 1) * 32;
    const int wn = (wid >> 1) * 32;
    const int nch = K / BK;

    const __half* pA = Ah + (size_t)row0 * K;
    const __half* pB = Bh + (size_t)col0 * K;

    const int lr = tid >> 2;
    const int lq = tid & 3;

    float acc[2][4][4];
#pragma unroll
    for (int f = 0; f < 2; f++)
#pragma unroll
        for (int j = 0; j < 4; j++)
#pragma unroll
            for (int i = 0; i < 4; i++) acc[f][j][i] = 0.f;

#define LOAD_STAGE(s_, c_)                                              \
    {                                                                   \
        uint32_t base_ = sb + (s_) * GSTAGE_BYTES;                      \
        size_t kof_ = (size_t)(c_) * BK;                                \
        uint32_t d_ = base_ + lr * ROWB + lq * 16;                      \
        size_t g_ = (size_t)lr * K + kof_ + lq * 8;                     \
        size_t g2_ = (size_t)(lr + 64) * K + kof_ + lq * 8;             \
        cp16(d_ + OFF_A, pA + g_);                                      \
        cp16(d_ + OFF_B, pB + g_);                                      \
        cp16(d_ + OFF_B + 64*ROWB, pB + g2_);                           \
    }

    LOAD_STAGE(0, 0);
    asm volatile("cp.async.commit_group;");
    LOAD_STAGE(1, 1);
    asm volatile("cp.async.commit_group;");

    for (int c = 0; c < nch; c++){
        asm volatile("cp.async.wait_group 1;");
        __syncthreads();

        if (c + 2 < nch){
            const int s2 = (c + 2) % 3;
            LOAD_STAGE(s2, c + 2);
        }
        asm volatile("cp.async.commit_group;");

        const uint32_t base = sb + (c % 3) * GSTAGE_BYTES;
#pragma unroll
        for (int ks = 0; ks < 2; ks++){
            const uint32_t kcol = (ks * 16 + (lane >> 4) * 8) * 2;
            uint32_t a[2][4], b[2][4];
#pragma unroll
            for (int f = 0; f < 2; f++){
                uint32_t ad = (wm + f * 16 + (lane & 15)) * ROWB + kcol;
                ldsm_x4(a[f][0], a[f][1], a[f][2], a[f][3], base + OFF_A + ad);
            }
#pragma unroll
            for (int g = 0; g < 2; g++){
                uint32_t bd = (wn + g * 16 + (lane & 15)) * ROWB + kcol;
                ldsm_x4(b[g][0], b[g][1], b[g][2], b[g][3], base + OFF_B + bd);
            }
#pragma unroll
            for (int f = 0; f < 2; f++)
#pragma unroll
                for (int j = 0; j < 4; j++){
                    const int g = j >> 1, o = j & 1;
                    mma16816(acc[f][j], a[f][0], a[f][1], a[f][2], a[f][3],
                             b[g][o], b[g][o + 2]);
                }
        }
    }

#pragma unroll
    for (int f = 0; f < 2; f++){
        const int row = row0 + wm + f * 16 + (lane >> 2);
#pragma unroll
        for (int j = 0; j < 4; j++){
            const int col = col0 + wn + j * 8 + (lane & 3) * 2;
            if (Cf){
                *(float2*)(Cf + (size_t)row * N + col)       = make_float2(acc[f][j][0], acc[f][j][1]);
                *(float2*)(Cf + (size_t)(row + 8) * N + col) = make_float2(acc[f][j][2], acc[f][j][3]);
            } else {
                *(uint32_t*)(Ch + (size_t)row * N + col)       = packh2(acc[f][j][0], acc[f][j][1]);
                *(uint32_t*)(Ch + (size_t)(row + 8) * N + col) = packh2(acc[f][j][2], acc[f][j][3]);
            }
        }
    }
}

// ---------------- fp16 flash attention: 128-q tile, 3-stage KV pipeline -----
#define RWB 144
#define AQ 0
#define KVBASE (128*RWB)                 // 18432
#define KVSTAGE (2*64*RWB)               // 18432 (K + V)
#define ATTN_SMEM (KVBASE + 3*KVSTAGE)   // 73728

__global__ __launch_bounds__(256) void attn_hmma(
    const __half* __restrict__ qkv, __half* __restrict__ oh)
{
    extern __shared__ char smc[];
    const uint32_t sb = s2u(smc);
    const int tid = threadIdx.x, lane = tid & 31, wid = tid >> 5;
    const int qt = blockIdx.x, bhid = blockIdx.y;
    const int b = bhid >> 4, h = bhid & 15;
    const int qs = qt * 128;
    const int wm = wid * 16;
    const size_t tok0 = (size_t)b * S_;

    // ---- load Q tile (pre-scaled by 0.125, exact in fp16) ----
    {
        const __half* qb = qkv + (tok0 + qs) * 3072 + h * 64;
        const __half2 sc = __half2half2(__float2half_rn(0.125f));
        for (int i = tid; i < 1024; i += 256){
            int r = i >> 3, q = i & 7;
            uint4 v = *(const uint4*)(qb + (size_t)r*3072 + q*8);
            __half2* p = (__half2*)&v;
            p[0] = __hmul2(p[0], sc); p[1] = __hmul2(p[1], sc);
            p[2] = __hmul2(p[2], sc); p[3] = __hmul2(p[3], sc);
            *(uint4*)(smc + AQ + r*RWB + q*16) = v;
        }
    }
    __syncthreads();

    uint32_t aq[4][4];
#pragma unroll
    for (int ks = 0; ks < 4; ks++){
        uint32_t ad = (uint32_t)((wm + (lane & 15)) * RWB + (ks*16 + (lane >> 4)*8) * 2);
        ldsm_x4(aq[ks][0], aq[ks][1], aq[ks][2], aq[ks][3], sb + AQ + ad);
    }

    float oacc[8][4];
#pragma unroll
    for (int f = 0; f < 8; f++)
#pragma unroll
        for (int e = 0; e < 4; e++) oacc[f][e] = 0.f;
    float m0 = -1e30f, m1 = -1e30f, l0 = 0.f, l1 = 0.f;

    const int ilo = qs + wm + (lane >> 2);
    const int ihi = ilo + 8;
    const int rmin = qs + wm;
    const int rmax = qs + wm + 15;

    const int js = qs - (WIN - 1);
    const int t0 = js > 0 ? (js >> 6) : 0;
    const int qe = (qs + 127) >> 6;

#define KV_LOAD(s_, jb_)                                                 \
    {                                                                    \
        uint32_t kbase_ = sb + KVBASE + (uint32_t)((s_) * KVSTAGE);      \
        uint32_t vbase_ = kbase_ + 64*RWB;                               \
        _Pragma("unroll")                                                \
        for (int u_ = 0; u_ < 2; u_++){                                  \
            int i_ = tid + u_*256;                                       \
            int r_ = i_ >> 3, q_ = i_ & 7;                               \
            size_t g_ = (tok0 + (jb_) + r_) * 3072 + h*64 + q_*8;        \
            cp16(kbase_ + r_*RWB + q_*16, qkv + g_ + 1024);              \
            cp16(vbase_ + r_*RWB + q_*16, qkv + g_ + 2048);              \
        }                                                                \
    }

    // prologue: tiles t0, t0+1 in flight (second only if it exists)
    KV_LOAD(0, t0 * 64);
    asm volatile("cp.async.commit_group;");
    if (t0 + 1 <= qe){
        KV_LOAD(1, (t0 + 1) * 64);
    }
    asm volatile("cp.async.commit_group;");

    for (int kt = t0; kt <= qe; kt++){
        const int jb = kt * 64;
        const int s = (kt - t0) % 3;
        // tile kt's group must be complete; kt+1's may remain in flight
        asm volatile("cp.async.wait_group 1;");
        __syncthreads();

        if (kt + 2 <= qe){
            KV_LOAD((kt + 2 - t0) % 3, jb + 128);
        }
        asm volatile("cp.async.commit_group;");

        // per-warp skip: tile fully outside [rmin-255, rmax] -> fully masked
        if (jb > rmax || jb + 63 < rmin - (WIN - 1)) continue;

        const uint32_t kb = sb + KVBASE + (uint32_t)(s * KVSTAGE);
        const uint32_t vb = kb + 64*RWB;

        float sacc[8][4];
#pragma unroll
        for (int f = 0; f < 8; f++)
#pragma unroll
            for (int e = 0; e < 4; e++) sacc[f][e] = 0.f;

#pragma unroll
        for (int g = 0; g < 4; g++){
#pragma unroll
            for (int ks = 0; ks < 4; ks++){
                uint32_t bd = (uint32_t)((g*16 + (lane & 15)) * RWB + (ks*16 + (lane >> 4)*8) * 2);
                uint32_t k0,k1,k2,k3;
                ldsm_x4(k0,k1,k2,k3, kb + bd);
                mma16816(sacc[2*g],   aq[ks][0],aq[ks][1],aq[ks][2],aq[ks][3], k0, k2);
                mma16816(sacc[2*g+1], aq[ks][0],aq[ks][1],aq[ks][2],aq[ks][3], k1, k3);
            }
        }

        float mx0 = -1e30f, mx1 = -1e30f;
#pragma unroll
        for (int f = 0; f < 8; f++){
            int c0 = jb + f*8 + 2*(lane & 3);
            int c1 = c0 + 1;
            sacc[f][0] = (c0 <= ilo && c0 > ilo - WIN) ? sacc[f][0] : -1e30f;
            sacc[f][1] = (c1 <= ilo && c1 > ilo - WIN) ? sacc[f][1] : -1e30f;
            sacc[f][2] = (c0 <= ihi && c0 > ihi - WIN) ? sacc[f][2] : -1e30f;
            sacc[f][3] = (c1 <= ihi && c1 > ihi - WIN) ? sacc[f][3] : -1e30f;
            mx0 = fmaxf(mx0, fmaxf(sacc[f][0], sacc[f][1]));
            mx1 = fmaxf(mx1, fmaxf(sacc[f][2], sacc[f][3]));
        }
        mx0 = fmaxf(mx0, __shfl_xor_sync(0xffffffffu, mx0, 1));
        mx0 = fmaxf(mx0, __shfl_xor_sync(0xffffffffu, mx0, 2));
        mx1 = fmaxf(mx1, __shfl_xor_sync(0xffffffffu, mx1, 1));
        mx1 = fmaxf(mx1, __shfl_xor_sync(0xffffffffu, mx1, 2));
        float mn0 = fmaxf(m0, mx0), mn1 = fmaxf(m1, mx1);
        float rc0 = __expf(m0 - mn0), rc1 = __expf(m1 - mn1);
        float rs0 = 0.f, rs1 = 0.f;
#pragma unroll
        for (int f = 0; f < 8; f++){
            sacc[f][0] = __expf(sacc[f][0] - mn0);
            sacc[f][1] = __expf(sacc[f][1] - mn0);
            sacc[f][2] = __expf(sacc[f][2] - mn1);
            sacc[f][3] = __expf(sacc[f][3] - mn1);
            rs0 += sacc[f][0] + sacc[f][1];
            rs1 += sacc[f][2] + sacc[f][3];
        }
        rs0 += __shfl_xor_sync(0xffffffffu, rs0, 1);
        rs0 += __shfl_xor_sync(0xffffffffu, rs0, 2);
        rs1 += __shfl_xor_sync(0xffffffffu, rs1, 1);
        rs1 += __shfl_xor_sync(0xffffffffu, rs1, 2);
        l0 = l0 * rc0 + rs0;  l1 = l1 * rc1 + rs1;
        m0 = mn0;  m1 = mn1;
#pragma unroll
        for (int f = 0; f < 8; f++){
            oacc[f][0] *= rc0; oacc[f][1] *= rc0;
            oacc[f][2] *= rc1; oacc[f][3] *= rc1;
        }

#pragma unroll
        for (int kk = 0; kk < 4; kk++){
            uint32_t pa[4];
            pa[0] = packh2(sacc[2*kk][0],   sacc[2*kk][1]);
            pa[1] = packh2(sacc[2*kk][2],   sacc[2*kk][3]);
            pa[2] = packh2(sacc[2*kk+1][0], sacc[2*kk+1][1]);
            pa[3] = packh2(sacc[2*kk+1][2], sacc[2*kk+1][3]);
#pragma unroll
            for (int j2 = 0; j2 < 4; j2++){
                uint32_t vd = (uint32_t)((kk*16 + ((lane >> 3) & 1)*8 + (lane & 7)) * RWB
                                         + (j2*16 + (lane >> 4)*8) * 2);
                uint32_t v0,v1,v2,v3;
                ldsm_x4t(v0,v1,v2,v3, vb + vd);
                mma16816(oacc[2*j2],   pa[0],pa[1],pa[2],pa[3], v0, v1);
                mma16816(oacc[2*j2+1], pa[0],pa[1],pa[2],pa[3], v2, v3);
            }
        }
    }

    float il0 = 1.f / l0, il1 = 1.f / l1;
    const int col = h*64 + 2*(lane & 3);
    size_t rowlo = (tok0 + ilo) * DM;
    size_t rowhi = (tok0 + ihi) * DM;
#pragma unroll
    for (int f = 0; f < 8; f++){
        *(uint32_t*)(oh + rowlo + col + f*8) = packh2(oacc[f][0]*il0, oacc[f][1]*il0);
        *(uint32_t*)(oh + rowhi + col + f*8) = packh2(oacc[f][2]*il1, oacc[f][3]*il1);
    }
}

// ---------------------------------------------------------------------------
extern "C" void kernel_launch(void* const* d_in, const int* in_sizes, int n_in,
                              void* d_out, int out_size)
{
    const float* x    = (const float*)d_in[0];
    const float* Wqkv = (const float*)d_in[1];
    const float* Wout = (const float*)d_in[2];
    float* out = (float*)d_out;

    __half *xh, *wq, *wo, *qkvh, *ah;
    cudaGetSymbolAddress((void**)&xh, g_xh);
    cudaGetSymbolAddress((void**)&wq, g_wqT);
    cudaGetSymbolAddress((void**)&wo, g_woT);
    cudaGetSymbolAddress((void**)&qkvh, g_qkvh);
    cudaGetSymbolAddress((void**)&ah, g_ah);

    cudaFuncSetAttribute(gemm_fp16, cudaFuncAttributeMaxDynamicSharedMemorySize, GEMM_SMEM);
    cudaFuncSetAttribute(attn_hmma, cudaFuncAttributeMaxDynamicSharedMemorySize, ATTN_SMEM);

    prep_all<<<8192, 256>>>(x, Wqkv, Wout, xh, wq, wo);
    gemm_fp16<<<dim3(3*DM/BN, MT/BM), 256, GEMM_SMEM>>>(xh, wq, qkvh, nullptr, MT, 3*DM, DM);
    attn_hmma<<<dim3(S_/128, B_*NH), 256, ATTN_SMEM>>>(qkvh, ah);
    gemm_fp16<<<dim3(DM/BN, MT/BM), 256, GEMM_SMEM>>>(ah, wo, nullptr, out, MT, DM, DM);
}

// round 16
// speedup vs baseline: 1.0537x; 1.0075x over previous
#include <cuda_runtime.h>
#include <cuda_fp16.h>
#include <math.h>
#include <stdint.h>

#define B_   2
#define S_   2048
#define DM   1024
#define NH   16
#define DH   64
#define WIN  256
#define MT   (B_*S_)

// ---------------- scratch (__device__ globals; no allocs allowed) ----------
__device__ __half g_xh[(size_t)MT * DM];
__device__ __half g_wqT[(size_t)3*DM*DM];
__device__ __half g_woT[(size_t)DM*DM];
__device__ __half g_qkvh[(size_t)MT*3*DM];
__device__ __half g_ah[(size_t)MT*DM];

// ---------------- helpers ---------------------------------------------------
__device__ __forceinline__ uint32_t s2u(const void* p){
    uint32_t a;
    asm("{ .reg .u64 t; cvta.to.shared.u64 t, %1; cvt.u32.u64 %0, t; }":"=r"(a):"l"(p));
    return a;
}
__device__ __forceinline__ void cp16(uint32_t dst, const void* src){
    asm volatile("cp.async.cg.shared.global [%0], [%1], 16;"::"r"(dst),"l"(src));
}
__device__ __forceinline__ void ldsm_x4(uint32_t& r0,uint32_t& r1,uint32_t& r2,uint32_t& r3,uint32_t addr){
    asm volatile("ldmatrix.sync.aligned.m8n8.x4.shared.b16 {%0,%1,%2,%3}, [%4];"
        : "=r"(r0),"=r"(r1),"=r"(r2),"=r"(r3) : "r"(addr));
}
__device__ __forceinline__ void ldsm_x4t(uint32_t& r0,uint32_t& r1,uint32_t& r2,uint32_t& r3,uint32_t addr){
    asm volatile("ldmatrix.sync.aligned.m8n8.x4.trans.shared.b16 {%0,%1,%2,%3}, [%4];"
        : "=r"(r0),"=r"(r1),"=r"(r2),"=r"(r3) : "r"(addr));
}
__device__ __forceinline__ void mma16816(float* c, uint32_t a0,uint32_t a1,uint32_t a2,uint32_t a3,
                                         uint32_t b0,uint32_t b1){
    asm volatile("mma.sync.aligned.m16n8k16.row.col.f32.f16.f16.f32 "
        "{%0,%1,%2,%3}, {%4,%5,%6,%7}, {%8,%9}, {%0,%1,%2,%3};"
        : "+f"(c[0]),"+f"(c[1]),"+f"(c[2]),"+f"(c[3])
        : "r"(a0),"r"(a1),"r"(a2),"r"(a3),"r"(b0),"r"(b1));
}
__device__ __forceinline__ uint32_t packh2(float x, float y){
    __half2 h = __floats2half2_rn(x, y);
    return *(uint32_t*)&h;
}

// ---------------- merged prep kernel ----------------------------------------
// sections: [0,2048) fhalf x (8 floats/thr) ; [2048,5120) thalf Wqkv ; [5120,6144) thalf Wout
__global__ __launch_bounds__(256) void prep_all(
    const float* __restrict__ x, const float* __restrict__ Wqkv,
    const float* __restrict__ Wout,
    __half* __restrict__ xh, __half* __restrict__ wq, __half* __restrict__ wo)
{
    __shared__ float t[32][33];
    const int bb = blockIdx.x;
    const int tid = threadIdx.x;

    if (bb < 2048){
        int i = (bb*256 + tid)*8;
        float4 v0 = *(const float4*)(x + i);
        float4 v1 = *(const float4*)(x + i + 4);
        *(__half2*)(xh + i)     = __floats2half2_rn(v0.x, v0.y);
        *(__half2*)(xh + i + 2) = __floats2half2_rn(v0.z, v0.w);
        *(__half2*)(xh + i + 4) = __floats2half2_rn(v1.x, v1.y);
        *(__half2*)(xh + i + 6) = __floats2half2_rn(v1.z, v1.w);
        return;
    }

    const float* W; __half* Th; int K, N, idx;
    if (bb < 5120){ idx = bb - 2048; W = Wqkv; Th = wq; K = DM; N = 3*DM; }
    else          { idx = bb - 5120; W = Wout; Th = wo; K = DM; N = DM;   }
    const int xdim = N/32;
    const int n0 = (idx % xdim)*32, k0 = (idx / xdim)*32;
    const int tx = tid & 31, ty = tid >> 5;
#pragma unroll
    for (int i = 0; i < 32; i += 8)
        t[ty+i][tx] = W[(size_t)(k0+ty+i)*N + n0+tx];
    __syncthreads();
#pragma unroll
    for (int i = 0; i < 32; i += 8)
        Th[(size_t)(n0+ty+i)*K + k0+tx] = __float2half_rn(t[tx][ty+i]);
}

// ---------------- pure fp16 HMMA GEMM, fp32 accum, 2 CTAs/SM (R13) ----------
#define BM 64
#define BN 128
#define BK 32
#define ROWB 80
#define OFF_A 0
#define OFF_B (BM*ROWB)
#define GSTAGE_BYTES ((BM+BN)*ROWB)          // 15360
#define GEMM_SMEM (3*GSTAGE_BYTES)           // 46080

__global__ __launch_bounds__(256, 2) void gemm_fp16(
    const __half* __restrict__ Ah, const __half* __restrict__ Bh,
    __half* __restrict__ Ch, float* __restrict__ Cf, int M, int N, int K)
{
    extern __shared__ char smraw[];
    const uint32_t sb = s2u(smraw);
    const int tid = threadIdx.x, lane = tid & 31, wid = tid >> 5;
    const int row0 = blockIdx.y * BM, col0 = blockIdx.x * BN;
    const int wm = (wid & 1) * 32;
    const int wn = (wid >> 1) * 32;
    const int nch = K / BK;

    const __half* pA = Ah + (size_t)row0 * K;
    const __half* pB = Bh + (size_t)col0 * K;

    const int lr = tid >> 2;
    const int lq = tid & 3;

    float acc[2][4][4];
#pragma unroll
    for (int f = 0; f < 2; f++)
#pragma unroll
        for (int j = 0; j < 4; j++)
#pragma unroll
            for (int i = 0; i < 4; i++) acc[f][j][i] = 0.f;

#define LOAD_STAGE(s_, c_)                                              \
    {                                                                   \
        uint32_t base_ = sb + (s_) * GSTAGE_BYTES;                      \
        size_t kof_ = (size_t)(c_) * BK;                                \
        uint32_t d_ = base_ + lr * ROWB + lq * 16;                      \
        size_t g_ = (size_t)lr * K + kof_ + lq * 8;                     \
        size_t g2_ = (size_t)(lr + 64) * K + kof_ + lq * 8;             \
        cp16(d_ + OFF_A, pA + g_);                                      \
        cp16(d_ + OFF_B, pB + g_);                                      \
        cp16(d_ + OFF_B + 64*ROWB, pB + g2_);                           \
    }

    LOAD_STAGE(0, 0);
    asm volatile("cp.async.commit_group;");
    LOAD_STAGE(1, 1);
    asm volatile("cp.async.commit_group;");

    for (int c = 0; c < nch; c++){
        asm volatile("cp.async.wait_group 1;");
        __syncthreads();

        if (c + 2 < nch){
            const int s2 = (c + 2) % 3;
            LOAD_STAGE(s2, c + 2);
        }
        asm volatile("cp.async.commit_group;");

        const uint32_t base = sb + (c % 3) * GSTAGE_BYTES;
#pragma unroll
        for (int ks = 0; ks < 2; ks++){
            const uint32_t kcol = (ks * 16 + (lane >> 4) * 8) * 2;
            uint32_t a[2][4], b[2][4];
#pragma unroll
            for (int f = 0; f < 2; f++){
                uint32_t ad = (wm + f * 16 + (lane & 15)) * ROWB + kcol;
                ldsm_x4(a[f][0], a[f][1], a[f][2], a[f][3], base + OFF_A + ad);
            }
#pragma unroll
            for (int g = 0; g < 2; g++){
                uint32_t bd = (wn + g * 16 + (lane & 15)) * ROWB + kcol;
                ldsm_x4(b[g][0], b[g][1], b[g][2], b[g][3], base + OFF_B + bd);
            }
#pragma unroll
            for (int f = 0; f < 2; f++)
#pragma unroll
                for (int j = 0; j < 4; j++){
                    const int g = j >> 1, o = j & 1;
                    mma16816(acc[f][j], a[f][0], a[f][1], a[f][2], a[f][3],
                             b[g][o], b[g][o + 2]);
                }
        }
    }

#pragma unroll
    for (int f = 0; f < 2; f++){
        const int row = row0 + wm + f * 16 + (lane >> 2);
#pragma unroll
        for (int j = 0; j < 4; j++){
            const int col = col0 + wn + j * 8 + (lane & 3) * 2;
            if (Cf){
                *(float2*)(Cf + (size_t)row * N + col)       = make_float2(acc[f][j][0], acc[f][j][1]);
                *(float2*)(Cf + (size_t)(row + 8) * N + col) = make_float2(acc[f][j][2], acc[f][j][3]);
            } else {
                *(uint32_t*)(Ch + (size_t)row * N + col)       = packh2(acc[f][j][0], acc[f][j][1]);
                *(uint32_t*)(Ch + (size_t)(row + 8) * N + col) = packh2(acc[f][j][2], acc[f][j][3]);
            }
        }
    }
}

// ---------------- fp16 flash attention: 128-q tile, 2-stage KV (R13) --------
#define RWB 144
#define AQ 0
#define KVBASE (128*RWB)                 // 18432
#define KVSTAGE (2*64*RWB)               // 18432 (K + V)
#define ATTN_SMEM (KVBASE + 2*KVSTAGE)   // 55296

__global__ __launch_bounds__(256) void attn_hmma(
    const __half* __restrict__ qkv, __half* __restrict__ oh)
{
    extern __shared__ char smc[];
    const uint32_t sb = s2u(smc);
    const int tid = threadIdx.x, lane = tid & 31, wid = tid >> 5;
    const int qt = blockIdx.x, bhid = blockIdx.y;
    const int b = bhid >> 4, h = bhid & 15;
    const int qs = qt * 128;
    const int wm = wid * 16;
    const size_t tok0 = (size_t)b * S_;

    // ---- load Q tile (pre-scaled by 0.125, exact in fp16) ----
    {
        const __half* qb = qkv + (tok0 + qs) * 3072 + h * 64;
        const __half2 sc = __half2half2(__float2half_rn(0.125f));
        for (int i = tid; i < 1024; i += 256){
            int r = i >> 3, q = i & 7;
            uint4 v = *(const uint4*)(qb + (size_t)r*3072 + q*8);
            __half2* p = (__half2*)&v;
            p[0] = __hmul2(p[0], sc); p[1] = __hmul2(p[1], sc);
            p[2] = __hmul2(p[2], sc); p[3] = __hmul2(p[3], sc);
            *(uint4*)(smc + AQ + r*RWB + q*16) = v;
        }
    }
    __syncthreads();

    uint32_t aq[4][4];
#pragma unroll
    for (int ks = 0; ks < 4; ks++){
        uint32_t ad = (uint32_t)((wm + (lane & 15)) * RWB + (ks*16 + (lane >> 4)*8) * 2);
        ldsm_x4(aq[ks][0], aq[ks][1], aq[ks][2], aq[ks][3], sb + AQ + ad);
    }

    float oacc[8][4];
#pragma unroll
    for (int f = 0; f < 8; f++)
#pragma unroll
        for (int e = 0; e < 4; e++) oacc[f][e] = 0.f;
    float m0 = -1e30f, m1 = -1e30f, l0 = 0.f, l1 = 0.f;

    const int ilo = qs + wm + (lane >> 2);
    const int ihi = ilo + 8;
    const int rmin = qs + wm;
    const int rmax = qs + wm + 15;

    const int js = qs - (WIN - 1);
    const int t0 = js > 0 ? (js >> 6) : 0;
    const int qe = (qs + 127) >> 6;

#define KV_LOAD(s_, jb_)                                                 \
    {                                                                    \
        uint32_t kbase_ = sb + KVBASE + (uint32_t)((s_) * KVSTAGE);      \
        uint32_t vbase_ = kbase_ + 64*RWB;                               \
        _Pragma("unroll")                                                \
        for (int u_ = 0; u_ < 2; u_++){                                  \
            int i_ = tid + u_*256;                                       \
            int r_ = i_ >> 3, q_ = i_ & 7;                               \
            size_t g_ = (tok0 + (jb_) + r_) * 3072 + h*64 + q_*8;        \
            cp16(kbase_ + r_*RWB + q_*16, qkv + g_ + 1024);              \
            cp16(vbase_ + r_*RWB + q_*16, qkv + g_ + 2048);              \
        }                                                                \
    }

    KV_LOAD(0, t0 * 64);
    asm volatile("cp.async.commit_group;");

    for (int kt = t0; kt <= qe; kt++){
        const int jb = kt * 64;
        const int s = (kt - t0) & 1;
        asm volatile("cp.async.wait_group 0;");
        __syncthreads();

        if (kt + 1 <= qe){
            KV_LOAD(s ^ 1, jb + 64);
        }
        asm volatile("cp.async.commit_group;");

        // per-warp skip: tile fully outside [rmin-255, rmax] -> fully masked
        if (jb > rmax || jb + 63 < rmin - (WIN - 1)) continue;

        const uint32_t kb = sb + KVBASE + (uint32_t)(s * KVSTAGE);
        const uint32_t vb = kb + 64*RWB;

        float sacc[8][4];
#pragma unroll
        for (int f = 0; f < 8; f++)
#pragma unroll
            for (int e = 0; e < 4; e++) sacc[f][e] = 0.f;

#pragma unroll
        for (int g = 0; g < 4; g++){
#pragma unroll
            for (int ks = 0; ks < 4; ks++){
                uint32_t bd = (uint32_t)((g*16 + (lane & 15)) * RWB + (ks*16 + (lane >> 4)*8) * 2);
                uint32_t k0,k1,k2,k3;
                ldsm_x4(k0,k1,k2,k3, kb + bd);
                mma16816(sacc[2*g],   aq[ks][0],aq[ks][1],aq[ks][2],aq[ks][3], k0, k2);
                mma16816(sacc[2*g+1], aq[ks][0],aq[ks][1],aq[ks][2],aq[ks][3], k1, k3);
            }
        }

        float mx0 = -1e30f, mx1 = -1e30f;
#pragma unroll
        for (int f = 0; f < 8; f++){
            int c0 = jb + f*8 + 2*(lane & 3);
            int c1 = c0 + 1;
            sacc[f][0] = (c0 <= ilo && c0 > ilo - WIN) ? sacc[f][0] : -1e30f;
            sacc[f][1] = (c1 <= ilo && c1 > ilo - WIN) ? sacc[f][1] : -1e30f;
            sacc[f][2] = (c0 <= ihi && c0 > ihi - WIN) ? sacc[f][2] : -1e30f;
            sacc[f][3] = (c1 <= ihi && c1 > ihi - WIN) ? sacc[f][3] : -1e30f;
            mx0 = fmaxf(mx0, fmaxf(sacc[f][0], sacc[f][1]));
            mx1 = fmaxf(mx1, fmaxf(sacc[f][2], sacc[f][3]));
        }
        mx0 = fmaxf(mx0, __shfl_xor_sync(0xffffffffu, mx0, 1));
        mx0 = fmaxf(mx0, __shfl_xor_sync(0xffffffffu, mx0, 2));
        mx1 = fmaxf(mx1, __shfl_xor_sync(0xffffffffu, mx1, 1));
        mx1 = fmaxf(mx1, __shfl_xor_sync(0xffffffffu, mx1, 2));
        float mn0 = fmaxf(m0, mx0), mn1 = fmaxf(m1, mx1);
        float rc0 = __expf(m0 - mn0), rc1 = __expf(m1 - mn1);
        float rs0 = 0.f, rs1 = 0.f;
#pragma unroll
        for (int f = 0; f < 8; f++){
            sacc[f][0] = __expf(sacc[f][0] - mn0);
            sacc[f][1] = __expf(sacc[f][1] - mn0);
            sacc[f][2] = __expf(sacc[f][2] - mn1);
            sacc[f][3] = __expf(sacc[f][3] - mn1);
            rs0 += sacc[f][0] + sacc[f][1];
            rs1 += sacc[f][2] + sacc[f][3];
        }
        rs0 += __shfl_xor_sync(0xffffffffu, rs0, 1);
        rs0 += __shfl_xor_sync(0xffffffffu, rs0, 2);
        rs1 += __shfl_xor_sync(0xffffffffu, rs1, 1);
        rs1 += __shfl_xor_sync(0xffffffffu, rs1, 2);
        l0 = l0 * rc0 + rs0;  l1 = l1 * rc1 + rs1;
        m0 = mn0;  m1 = mn1;
#pragma unroll
        for (int f = 0; f < 8; f++){
            oacc[f][0] *= rc0; oacc[f][1] *= rc0;
            oacc[f][2] *= rc1; oacc[f][3] *= rc1;
        }

#pragma unroll
        for (int kk = 0; kk < 4; kk++){
            uint32_t pa[4];
            pa[0] = packh2(sacc[2*kk][0],   sacc[2*kk][1]);
            pa[1] = packh2(sacc[2*kk][2],   sacc[2*kk][3]);
            pa[2] = packh2(sacc[2*kk+1][0], sacc[2*kk+1][1]);
            pa[3] = packh2(sacc[2*kk+1][2], sacc[2*kk+1][3]);
#pragma unroll
            for (int j2 = 0; j2 < 4; j2++){
                uint32_t vd = (uint32_t)((kk*16 + ((lane >> 3) & 1)*8 + (lane & 7)) * RWB
                                         + (j2*16 + (lane >> 4)*8) * 2);
                uint32_t v0,v1,v2,v3;
                ldsm_x4t(v0,v1,v2,v3, vb + vd);
                mma16816(oacc[2*j2],   pa[0],pa[1],pa[2],pa[3], v0, v1);
                mma16816(oacc[2*j2+1], pa[0],pa[1],pa[2],pa[3], v2, v3);
            }
        }
    }

    float il0 = 1.f / l0, il1 = 1.f / l1;
    const int col = h*64 + 2*(lane & 3);
    size_t rowlo = (tok0 + ilo) * DM;
    size_t rowhi = (tok0 + ihi) * DM;
#pragma unroll
    for (int f = 0; f < 8; f++){
        *(uint32_t*)(oh + rowlo + col + f*8) = packh2(oacc[f][0]*il0, oacc[f][1]*il0);
        *(uint32_t*)(oh + rowhi + col + f*8) = packh2(oacc[f][2]*il1, oacc[f][3]*il1);
    }
}

// ---------------------------------------------------------------------------
extern "C" void kernel_launch(void* const* d_in, const int* in_sizes, int n_in,
                              void* d_out, int out_size)
{
    const float* x    = (const float*)d_in[0];
    const float* Wqkv = (const float*)d_in[1];
    const float* Wout = (const float*)d_in[2];
    float* out = (float*)d_out;

    __half *xh, *wq, *wo, *qkvh, *ah;
    cudaGetSymbolAddress((void**)&xh, g_xh);
    cudaGetSymbolAddress((void**)&wq, g_wqT);
    cudaGetSymbolAddress((void**)&wo, g_woT);
    cudaGetSymbolAddress((void**)&qkvh, g_qkvh);
    cudaGetSymbolAddress((void**)&ah, g_ah);

    cudaFuncSetAttribute(gemm_fp16, cudaFuncAttributeMaxDynamicSharedMemorySize, GEMM_SMEM);
    cudaFuncSetAttribute(attn_hmma, cudaFuncAttributeMaxDynamicSharedMemorySize, ATTN_SMEM);

    prep_all<<<6144, 256>>>(x, Wqkv, Wout, xh, wq, wo);
    gemm_fp16<<<dim3(3*DM/BN, MT/BM), 256, GEMM_SMEM>>>(xh, wq, qkvh, nullptr, MT, 3*DM, DM);
    attn_hmma<<<dim3(S_/128, B_*NH), 256, ATTN_SMEM>>>(qkvh, ah);
    gemm_fp16<<<dim3(DM/BN, MT/BM), 256, GEMM_SMEM>>>(ah, wo, nullptr, out, MT, DM, DM);
}

// round 17
// speedup vs baseline: 1.0539x; 1.0002x over previous
#include <cuda_runtime.h>
#include <cuda_fp16.h>
#include <math.h>
#include <stdint.h>

#define B_   2
#define S_   2048
#define DM   1024
#define NH   16
#define DH   64
#define WIN  256
#define MT   (B_*S_)

// ---------------- scratch (__device__ globals; no allocs allowed) ----------
__device__ __half g_xh[(size_t)MT * DM];
__device__ __half g_wqT[(size_t)3*DM*DM];
__device__ __half g_woT[(size_t)DM*DM];
__device__ __half g_qkvh[(size_t)MT*3*DM];
__device__ __half g_ah[(size_t)MT*DM];

// ---------------- helpers ---------------------------------------------------
__device__ __forceinline__ uint32_t s2u(const void* p){
    uint32_t a;
    asm("{ .reg .u64 t; cvta.to.shared.u64 t, %1; cvt.u32.u64 %0, t; }":"=r"(a):"l"(p));
    return a;
}
__device__ __forceinline__ void cp16(uint32_t dst, const void* src){
    asm volatile("cp.async.cg.shared.global [%0], [%1], 16;"::"r"(dst),"l"(src));
}
__device__ __forceinline__ void ldsm_x4(uint32_t& r0,uint32_t& r1,uint32_t& r2,uint32_t& r3,uint32_t addr){
    asm volatile("ldmatrix.sync.aligned.m8n8.x4.shared.b16 {%0,%1,%2,%3}, [%4];"
        : "=r"(r0),"=r"(r1),"=r"(r2),"=r"(r3) : "r"(addr));
}
__device__ __forceinline__ void ldsm_x4t(uint32_t& r0,uint32_t& r1,uint32_t& r2,uint32_t& r3,uint32_t addr){
    asm volatile("ldmatrix.sync.aligned.m8n8.x4.trans.shared.b16 {%0,%1,%2,%3}, [%4];"
        : "=r"(r0),"=r"(r1),"=r"(r2),"=r"(r3) : "r"(addr));
}
__device__ __forceinline__ void mma16816(float* c, uint32_t a0,uint32_t a1,uint32_t a2,uint32_t a3,
                                         uint32_t b0,uint32_t b1){
    asm volatile("mma.sync.aligned.m16n8k16.row.col.f32.f16.f16.f32 "
        "{%0,%1,%2,%3}, {%4,%5,%6,%7}, {%8,%9}, {%0,%1,%2,%3};"
        : "+f"(c[0]),"+f"(c[1]),"+f"(c[2]),"+f"(c[3])
        : "r"(a0),"r"(a1),"r"(a2),"r"(a3),"r"(b0),"r"(b1));
}
__device__ __forceinline__ uint32_t packh2(float x, float y){
    __half2 h = __floats2half2_rn(x, y);
    return *(uint32_t*)&h;
}

// ---------------- merged prep kernel ----------------------------------------
// sections: [0,2048) fhalf x (8 floats/thr) ; [2048,5120) thalf Wqkv ; [5120,6144) thalf Wout
__global__ __launch_bounds__(256) void prep_all(
    const float* __restrict__ x, const float* __restrict__ Wqkv,
    const float* __restrict__ Wout,
    __half* __restrict__ xh, __half* __restrict__ wq, __half* __restrict__ wo)
{
    __shared__ float t[32][33];
    const int bb = blockIdx.x;
    const int tid = threadIdx.x;

    if (bb < 2048){
        int i = (bb*256 + tid)*8;
        float4 v0 = *(const float4*)(x + i);
        float4 v1 = *(const float4*)(x + i + 4);
        *(__half2*)(xh + i)     = __floats2half2_rn(v0.x, v0.y);
        *(__half2*)(xh + i + 2) = __floats2half2_rn(v0.z, v0.w);
        *(__half2*)(xh + i + 4) = __floats2half2_rn(v1.x, v1.y);
        *(__half2*)(xh + i + 6) = __floats2half2_rn(v1.z, v1.w);
        return;
    }

    const float* W; __half* Th; int K, N, idx;
    if (bb < 5120){ idx = bb - 2048; W = Wqkv; Th = wq; K = DM; N = 3*DM; }
    else          { idx = bb - 5120; W = Wout; Th = wo; K = DM; N = DM;   }
    const int xdim = N/32;
    const int n0 = (idx % xdim)*32, k0 = (idx / xdim)*32;
    const int tx = tid & 31, ty = tid >> 5;
#pragma unroll
    for (int i = 0; i < 32; i += 8)
        t[ty+i][tx] = W[(size_t)(k0+ty+i)*N + n0+tx];
    __syncthreads();
#pragma unroll
    for (int i = 0; i < 32; i += 8)
        Th[(size_t)(n0+ty+i)*K + k0+tx] = __float2half_rn(t[tx][ty+i]);
}

// ---------------- pure fp16 HMMA GEMM, 128x128 tile, fp32 accum -------------
#define BM 128
#define BN 128
#define BK 32
#define ROWB 80
#define OFF_A 0
#define OFF_B (BM*ROWB)
#define GSTAGE_BYTES ((BM+BN)*ROWB)          // 20480
#define GEMM_SMEM (3*GSTAGE_BYTES)           // 61440

__global__ __launch_bounds__(256, 2) void gemm_fp16(
    const __half* __restrict__ Ah, const __half* __restrict__ Bh,
    __half* __restrict__ Ch, float* __restrict__ Cf, int M, int N, int K)
{
    extern __shared__ char smraw[];
    const uint32_t sb = s2u(smraw);
    const int tid = threadIdx.x, lane = tid & 31, wid = tid >> 5;
    const int row0 = blockIdx.y * BM, col0 = blockIdx.x * BN;
    const int wm = (wid & 1) * 64;    // 2 warps in M, warp tile 64 rows
    const int wn = (wid >> 1) * 32;   // 4 warps in N, 32 cols
    const int nch = K / BK;

    const __half* pA = Ah + (size_t)row0 * K;
    const __half* pB = Bh + (size_t)col0 * K;

    const int lr = tid >> 2;          // 0..63
    const int lq = tid & 3;

    float acc[4][4][4];
#pragma unroll
    for (int f = 0; f < 4; f++)
#pragma unroll
        for (int j = 0; j < 4; j++)
#pragma unroll
            for (int i = 0; i < 4; i++) acc[f][j][i] = 0.f;

#define LOAD_STAGE(s_, c_)                                              \
    {                                                                   \
        uint32_t base_ = sb + (s_) * GSTAGE_BYTES;                      \
        size_t kof_ = (size_t)(c_) * BK;                                \
        uint32_t d_ = base_ + lr * ROWB + lq * 16;                      \
        size_t g_ = (size_t)lr * K + kof_ + lq * 8;                     \
        size_t g2_ = (size_t)(lr + 64) * K + kof_ + lq * 8;             \
        cp16(d_ + OFF_A, pA + g_);                                      \
        cp16(d_ + OFF_A + 64*ROWB, pA + g2_);                           \
        cp16(d_ + OFF_B, pB + g_);                                      \
        cp16(d_ + OFF_B + 64*ROWB, pB + g2_);                           \
    }

    LOAD_STAGE(0, 0);
    asm volatile("cp.async.commit_group;");
    LOAD_STAGE(1, 1);
    asm volatile("cp.async.commit_group;");

    for (int c = 0; c < nch; c++){
        asm volatile("cp.async.wait_group 1;");
        __syncthreads();

        if (c + 2 < nch){
            const int s2 = (c + 2) % 3;
            LOAD_STAGE(s2, c + 2);
        }
        asm volatile("cp.async.commit_group;");

        const uint32_t base = sb + (c % 3) * GSTAGE_BYTES;
#pragma unroll
        for (int ks = 0; ks < 2; ks++){
            const uint32_t kcol = (ks * 16 + (lane >> 4) * 8) * 2;
            uint32_t a[4][4], b[2][4];
#pragma unroll
            for (int f = 0; f < 4; f++){
                uint32_t ad = (wm + f * 16 + (lane & 15)) * ROWB + kcol;
                ldsm_x4(a[f][0], a[f][1], a[f][2], a[f][3], base + OFF_A + ad);
            }
#pragma unroll
            for (int g = 0; g < 2; g++){
                uint32_t bd = (wn + g * 16 + (lane & 15)) * ROWB + kcol;
                ldsm_x4(b[g][0], b[g][1], b[g][2], b[g][3], base + OFF_B + bd);
            }
#pragma unroll
            for (int f = 0; f < 4; f++)
#pragma unroll
                for (int j = 0; j < 4; j++){
                    const int g = j >> 1, o = j & 1;
                    mma16816(acc[f][j], a[f][0], a[f][1], a[f][2], a[f][3],
                             b[g][o], b[g][o + 2]);
                }
        }
    }

#pragma unroll
    for (int f = 0; f < 4; f++){
        const int row = row0 + wm + f * 16 + (lane >> 2);
#pragma unroll
        for (int j = 0; j < 4; j++){
            const int col = col0 + wn + j * 8 + (lane & 3) * 2;
            if (Cf){
                *(float2*)(Cf + (size_t)row * N + col)       = make_float2(acc[f][j][0], acc[f][j][1]);
                *(float2*)(Cf + (size_t)(row + 8) * N + col) = make_float2(acc[f][j][2], acc[f][j][3]);
            } else {
                *(uint32_t*)(Ch + (size_t)row * N + col)       = packh2(acc[f][j][0], acc[f][j][1]);
                *(uint32_t*)(Ch + (size_t)(row + 8) * N + col) = packh2(acc[f][j][2], acc[f][j][3]);
            }
        }
    }
}

// ---------------- fp16 flash attention: 128-q tile, 2-stage KV (R13) --------
#define RWB 144
#define AQ 0
#define KVBASE (128*RWB)                 // 18432
#define KVSTAGE (2*64*RWB)               // 18432 (K + V)
#define ATTN_SMEM (KVBASE + 2*KVSTAGE)   // 55296

__global__ __launch_bounds__(256) void attn_hmma(
    const __half* __restrict__ qkv, __half* __restrict__ oh)
{
    extern __shared__ char smc[];
    const uint32_t sb = s2u(smc);
    const int tid = threadIdx.x, lane = tid & 31, wid = tid >> 5;
    const int qt = blockIdx.x, bhid = blockIdx.y;
    const int b = bhid >> 4, h = bhid & 15;
    const int qs = qt * 128;
    const int wm = wid * 16;
    const size_t tok0 = (size_t)b * S_;

    // ---- load Q tile (pre-scaled by 0.125, exact in fp16) ----
    {
        const __half* qb = qkv + (tok0 + qs) * 3072 + h * 64;
        const __half2 sc = __half2half2(__float2half_rn(0.125f));
        for (int i = tid; i < 1024; i += 256){
            int r = i >> 3, q = i & 7;
            uint4 v = *(const uint4*)(qb + (size_t)r*3072 + q*8);
            __half2* p = (__half2*)&v;
            p[0] = __hmul2(p[0], sc); p[1] = __hmul2(p[1], sc);
            p[2] = __hmul2(p[2], sc); p[3] = __hmul2(p[3], sc);
            *(uint4*)(smc + AQ + r*RWB + q*16) = v;
        }
    }
    __syncthreads();

    uint32_t aq[4][4];
#pragma unroll
    for (int ks = 0; ks < 4; ks++){
        uint32_t ad = (uint32_t)((wm + (lane & 15)) * RWB + (ks*16 + (lane >> 4)*8) * 2);
        ldsm_x4(aq[ks][0], aq[ks][1], aq[ks][2], aq[ks][3], sb + AQ + ad);
    }

    float oacc[8][4];
#pragma unroll
    for (int f = 0; f < 8; f++)
#pragma unroll
        for (int e = 0; e < 4; e++) oacc[f][e] = 0.f;
    float m0 = -1e30f, m1 = -1e30f, l0 = 0.f, l1 = 0.f;

    const int ilo = qs + wm + (lane >> 2);
    const int ihi = ilo + 8;
    const int rmin = qs + wm;
    const int rmax = qs + wm + 15;

    const int js = qs - (WIN - 1);
    const int t0 = js > 0 ? (js >> 6) : 0;
    const int qe = (qs + 127) >> 6;

#define KV_LOAD(s_, jb_)                                                 \
    {                                                                    \
        uint32_t kbase_ = sb + KVBASE + (uint32_t)((s_) * KVSTAGE);      \
        uint32_t vbase_ = kbase_ + 64*RWB;                               \
        _Pragma("unroll")                                                \
        for (int u_ = 0; u_ < 2; u_++){                                  \
            int i_ = tid + u_*256;                                       \
            int r_ = i_ >> 3, q_ = i_ & 7;                               \
            size_t g_ = (tok0 + (jb_) + r_) * 3072 + h*64 + q_*8;        \
            cp16(kbase_ + r_*RWB + q_*16, qkv + g_ + 1024);              \
            cp16(vbase_ + r_*RWB + q_*16, qkv + g_ + 2048);              \
        }                                                                \
    }

    KV_LOAD(0, t0 * 64);
    asm volatile("cp.async.commit_group;");

    for (int kt = t0; kt <= qe; kt++){
        const int jb = kt * 64;
        const int s = (kt - t0) & 1;
        asm volatile("cp.async.wait_group 0;");
        __syncthreads();

        if (kt + 1 <= qe){
            KV_LOAD(s ^ 1, jb + 64);
        }
        asm volatile("cp.async.commit_group;");

        // per-warp skip: tile fully outside [rmin-255, rmax] -> fully masked
        if (jb > rmax || jb + 63 < rmin - (WIN - 1)) continue;

        const uint32_t kb = sb + KVBASE + (uint32_t)(s * KVSTAGE);
        const uint32_t vb = kb + 64*RWB;

        float sacc[8][4];
#pragma unroll
        for (int f = 0; f < 8; f++)
#pragma unroll
            for (int e = 0; e < 4; e++) sacc[f][e] = 0.f;

#pragma unroll
        for (int g = 0; g < 4; g++){
#pragma unroll
            for (int ks = 0; ks < 4; ks++){
                uint32_t bd = (uint32_t)((g*16 + (lane & 15)) * RWB + (ks*16 + (lane >> 4)*8) * 2);
                uint32_t k0,k1,k2,k3;
                ldsm_x4(k0,k1,k2,k3, kb + bd);
                mma16816(sacc[2*g],   aq[ks][0],aq[ks][1],aq[ks][2],aq[ks][3], k0, k2);
                mma16816(sacc[2*g+1], aq[ks][0],aq[ks][1],aq[ks][2],aq[ks][3], k1, k3);
            }
        }

        float mx0 = -1e30f, mx1 = -1e30f;
#pragma unroll
        for (int f = 0; f < 8; f++){
            int c0 = jb + f*8 + 2*(lane & 3);
            int c1 = c0 + 1;
            sacc[f][0] = (c0 <= ilo && c0 > ilo - WIN) ? sacc[f][0] : -1e30f;
            sacc[f][1] = (c1 <= ilo && c1 > ilo - WIN) ? sacc[f][1] : -1e30f;
            sacc[f][2] = (c0 <= ihi && c0 > ihi - WIN) ? sacc[f][2] : -1e30f;
            sacc[f][3] = (c1 <= ihi && c1 > ihi - WIN) ? sacc[f][3] : -1e30f;
            mx0 = fmaxf(mx0, fmaxf(sacc[f][0], sacc[f][1]));
            mx1 = fmaxf(mx1, fmaxf(sacc[f][2], sacc[f][3]));
        }
        mx0 = fmaxf(mx0, __shfl_xor_sync(0xffffffffu, mx0, 1));
        mx0 = fmaxf(mx0, __shfl_xor_sync(0xffffffffu, mx0, 2));
        mx1 = fmaxf(mx1, __shfl_xor_sync(0xffffffffu, mx1, 1));
        mx1 = fmaxf(mx1, __shfl_xor_sync(0xffffffffu, mx1, 2));
        float mn0 = fmaxf(m0, mx0), mn1 = fmaxf(m1, mx1);
        float rc0 = __expf(m0 - mn0), rc1 = __expf(m1 - mn1);
        float rs0 = 0.f, rs1 = 0.f;
#pragma unroll
        for (int f = 0; f < 8; f++){
            sacc[f][0] = __expf(sacc[f][0] - mn0);
            sacc[f][1] = __expf(sacc[f][1] - mn0);
            sacc[f][2] = __expf(sacc[f][2] - mn1);
            sacc[f][3] = __expf(sacc[f][3] - mn1);
            rs0 += sacc[f][0] + sacc[f][1];
            rs1 += sacc[f][2] + sacc[f][3];
        }
        rs0 += __shfl_xor_sync(0xffffffffu, rs0, 1);
        rs0 += __shfl_xor_sync(0xffffffffu, rs0, 2);
        rs1 += __shfl_xor_sync(0xffffffffu, rs1, 1);
        rs1 += __shfl_xor_sync(0xffffffffu, rs1, 2);
        l0 = l0 * rc0 + rs0;  l1 = l1 * rc1 + rs1;
        m0 = mn0;  m1 = mn1;
#pragma unroll
        for (int f = 0; f < 8; f++){
            oacc[f][0] *= rc0; oacc[f][1] *= rc0;
            oacc[f][2] *= rc1; oacc[f][3] *= rc1;
        }

#pragma unroll
        for (int kk = 0; kk < 4; kk++){
            uint32_t pa[4];
            pa[0] = packh2(sacc[2*kk][0],   sacc[2*kk][1]);
            pa[1] = packh2(sacc[2*kk][2],   sacc[2*kk][3]);
            pa[2] = packh2(sacc[2*kk+1][0], sacc[2*kk+1][1]);
            pa[3] = packh2(sacc[2*kk+1][2], sacc[2*kk+1][3]);
#pragma unroll
            for (int j2 = 0; j2 < 4; j2++){
                uint32_t vd = (uint32_t)((kk*16 + ((lane >> 3) & 1)*8 + (lane & 7)) * RWB
                                         + (j2*16 + (lane >> 4)*8) * 2);
                uint32_t v0,v1,v2,v3;
                ldsm_x4t(v0,v1,v2,v3, vb + vd);
                mma16816(oacc[2*j2],   pa[0],pa[1],pa[2],pa[3], v0, v1);
                mma16816(oacc[2*j2+1], pa[0],pa[1],pa[2],pa[3], v2, v3);
            }
        }
    }

    float il0 = 1.f / l0, il1 = 1.f / l1;
    const int col = h*64 + 2*(lane & 3);
    size_t rowlo = (tok0 + ilo) * DM;
    size_t rowhi = (tok0 + ihi) * DM;
#pragma unroll
    for (int f = 0; f < 8; f++){
        *(uint32_t*)(oh + rowlo + col + f*8) = packh2(oacc[f][0]*il0, oacc[f][1]*il0);
        *(uint32_t*)(oh + rowhi + col + f*8) = packh2(oacc[f][2]*il1, oacc[f][3]*il1);
    }
}

// ---------------------------------------------------------------------------
extern "C" void kernel_launch(void* const* d_in, const int* in_sizes, int n_in,
                              void* d_out, int out_size)
{
    const float* x    = (const float*)d_in[0];
    const float* Wqkv = (const float*)d_in[1];
    const float* Wout = (const float*)d_in[2];
    float* out = (float*)d_out;

    __half *xh, *wq, *wo, *qkvh, *ah;
    cudaGetSymbolAddress((void**)&xh, g_xh);
    cudaGetSymbolAddress((void**)&wq, g_wqT);
    cudaGetSymbolAddress((void**)&wo, g_woT);
    cudaGetSymbolAddress((void**)&qkvh, g_qkvh);
    cudaGetSymbolAddress((void**)&ah, g_ah);

    cudaFuncSetAttribute(gemm_fp16, cudaFuncAttributeMaxDynamicSharedMemorySize, GEMM_SMEM);
    cudaFuncSetAttribute(attn_hmma, cudaFuncAttributeMaxDynamicSharedMemorySize, ATTN_SMEM);

    prep_all<<<6144, 256>>>(x, Wqkv, Wout, xh, wq, wo);
    gemm_fp16<<<dim3(3*DM/BN, MT/BM), 256, GEMM_SMEM>>>(xh, wq, qkvh, nullptr, MT, 3*DM, DM);
    attn_hmma<<<dim3(S_/128, B_*NH), 256, ATTN_SMEM>>>(qkvh, ah);
    gemm_fp16<<<dim3(DM/BN, MT/BM), 256, GEMM_SMEM>>>(ah, wo, nullptr, out, MT, DM, DM);
}